// round 15
// baseline (speedup 1.0000x reference)
#include <cuda_runtime.h>
#include <cuda_bf16.h>
#include <cstdint>

#define BF __nv_bfloat16
#define SCALE_ 0.17677669529663687f

// ---------------- scratch ----------------
__device__ __align__(16) BF    g_A  [2048u*4096u];
__device__ __align__(16) BF    g_wsr[1048576];
__device__ __align__(16) BF    g_wq [65536], g_wkv[131072], g_wo[65536];
__device__ __align__(16) float g_prt[8u*2048u*256u];
__device__ __align__(16) BF    g_xr [2048u*256u];
__device__ __align__(16) BF    g_kv [2048u*512u];
__device__ __align__(16) BF    g_xT [32768u*256u];
__device__ __align__(16) BF    g_qb [32768u*256u];
__device__ __align__(16) BF    g_ao [32768u*256u];
__device__ __align__(16) BF    g_vt [64u*8192u];

__device__ __forceinline__ uint32_t pk(float a, float b) {
    __nv_bfloat162 t; t.x = __float2bfloat16(a); t.y = __float2bfloat16(b);
    return *reinterpret_cast<uint32_t*>(&t);
}
__device__ __forceinline__ void mma16816(float* d, const uint32_t* a, const uint32_t* b) {
    asm volatile("mma.sync.aligned.m16n8k16.row.col.f32.bf16.bf16.f32 "
                 "{%0,%1,%2,%3}, {%4,%5,%6,%7}, {%8,%9}, {%0,%1,%2,%3};"
                 : "+f"(d[0]), "+f"(d[1]), "+f"(d[2]), "+f"(d[3])
                 : "r"(a[0]), "r"(a[1]), "r"(a[2]), "r"(a[3]), "r"(b[0]), "r"(b[1]));
}
__device__ __forceinline__ void ldsm4(uint32_t* r, const BF* p) {
    uint32_t a = (uint32_t)__cvta_generic_to_shared(p);
    asm volatile("ldmatrix.sync.aligned.m8n8.x4.shared.b16 {%0,%1,%2,%3}, [%4];"
                 : "=r"(r[0]), "=r"(r[1]), "=r"(r[2]), "=r"(r[3]) : "r"(a));
}
__device__ __forceinline__ void ldsmA(uint32_t* r, const BF* base, int mb, int kb, int ld, int lane) {
    int sel = lane >> 3, i = lane & 7;
    ldsm4(r, base + (mb + ((sel & 1) << 3) + i) * ld + kb + ((sel >> 1) << 3));
}
__device__ __forceinline__ void ldsmB(uint32_t* r, const BF* base, int nb, int kb, int ld, int lane) {
    int sel = lane >> 3, i = lane & 7;
    ldsm4(r, base + (nb + ((sel >> 1) << 3) + i) * ld + kb + ((sel & 1) << 3));
}
#define CP_ASYNC16(dst, src) \
    asm volatile("cp.async.cg.shared.global [%0], [%1], 16;\n" :: "r"(dst), "l"(src))
#define CP_COMMIT() asm volatile("cp.async.commit_group;\n" ::: "memory")
#define CP_WAIT1()  asm volatile("cp.async.wait_group 1;\n" ::: "memory")

// ---------------- merged prep ----------------
__global__ void prep_k(const float* __restrict__ x,
                       const float* __restrict__ wq, const float* __restrict__ wkv,
                       const float* __restrict__ wsr, const float* __restrict__ wo,
                       BF* __restrict__ dq, BF* __restrict__ dkv,
                       BF* __restrict__ dsr, BF* __restrict__ dwo,
                       BF* __restrict__ A, BF* __restrict__ T)
{
    __shared__ __align__(16) BF sm[32 * 264];
    int bx = blockIdx.x, tid = threadIdx.x;
    if (bx < 1280) {
        int i = bx * 256 + tid;
        const float* s; BF* d; int o;
        if (i < 16384)       { s = wq;  d = dq;  o = i; }
        else if (i < 49152)  { s = wkv; d = dkv; o = i - 16384; }
        else if (i < 311296) { s = wsr; d = dsr; o = i - 49152; }
        else                 { s = wo;  d = dwo; o = i - 311296; }
        float4 v = ((const float4*)s)[o];
        ((uint2*)d)[o] = make_uint2(pk(v.x, v.y), pk(v.z, v.w));
    } else {
        int idx = bx - 1280;
        int c0 = (idx & 7) * 32, i = (idx >> 3) & 15, b = idx >> 7;
#pragma unroll
        for (int it = 0; it < 32; it++) {
            int g = tid + 256 * it;
            int col = g & 255, cc = g >> 8;
            float v = x[(long)b * 1048576 + (long)(c0 + cc) * 4096 + i * 256 + col];
            sm[cc * 264 + col] = __float2bfloat16(v);
        }
        __syncthreads();
#pragma unroll
        for (int it = 0; it < 4; it++) {
            int g = tid + 256 * it;
            int j = g >> 6, rem = g & 63;
            int cc = rem >> 1, hb = (rem & 1) * 2;
            __align__(16) BF tmp[8];
#pragma unroll
            for (int r1o = 0; r1o < 2; r1o++)
#pragma unroll
                for (int r2 = 0; r2 < 4; r2++)
                    tmp[r1o * 4 + r2] = sm[cc * 264 + (hb + r1o) * 64 + 4 * j + r2];
            *(uint4*)(A + ((long)(b * 256 + i * 16 + j)) * 4096 + c0 * 16 + rem * 8) = *(uint4*)tmp;
        }
#pragma unroll
        for (int it = 0; it < 4; it++) {
            int g = tid + 256 * it;
            int nl = g >> 2, c8 = g & 3;
            __align__(16) BF tmp[8];
#pragma unroll
            for (int t = 0; t < 8; t++) tmp[t] = sm[(c8 * 8 + t) * 264 + nl];
            *(uint4*)(T + ((long)(b * 4096 + i * 256 + nl)) * 256 + c0 + c8 * 8) = *(uint4*)tmp;
        }
    }
}
__global__ void lnred_k(const float* __restrict__ part, const float* __restrict__ gam,
                        const float* __restrict__ bet, BF* __restrict__ o) {
    __shared__ float sm1[4][2], sm2[4][2];
    int tid = threadIdx.x;
    int r = tid >> 6, t64 = tid & 63, lane = tid & 31, wir = (tid >> 5) & 1;
    int p = blockIdx.x * 4 + r;
    long base = (long)p * 256 + t64 * 4;
    float4 v = make_float4(0.f, 0.f, 0.f, 0.f);
#pragma unroll
    for (int z = 0; z < 8; z++) {
        float4 t = *(const float4*)(part + (long)z * 524288 + base);
        v.x += t.x; v.y += t.y; v.z += t.z; v.w += t.w;
    }
    float s1 = v.x + v.y + v.z + v.w;
    float s2 = v.x * v.x + v.y * v.y + v.z * v.z + v.w * v.w;
#pragma unroll
    for (int off = 16; off; off >>= 1) {
        s1 += __shfl_xor_sync(0xffffffffu, s1, off);
        s2 += __shfl_xor_sync(0xffffffffu, s2, off);
    }
    if (lane == 0) { sm1[r][wir] = s1; sm2[r][wir] = s2; }
    __syncthreads();
    float a = sm1[r][0] + sm1[r][1];
    float q = sm2[r][0] + sm2[r][1];
    float mu = a * (1.f / 256.f);
    float inv = rsqrtf(q * (1.f / 256.f) - mu * mu + 1e-6f);
    float4 gv = *(const float4*)(gam + t64 * 4);
    float4 bv = *(const float4*)(bet + t64 * 4);
    uint2 w;
    w.x = pk((v.x - mu) * inv * gv.x + bv.x, (v.y - mu) * inv * gv.y + bv.y);
    w.y = pk((v.z - mu) * inv * gv.z + bv.z, (v.w - mu) * inv * gv.w + bv.w);
    *(uint2*)(o + base) = w;
}
__global__ void vtp_k(const BF* __restrict__ kv, BF* __restrict__ vt) {
    int bh = blockIdx.x, b = bh >> 3, h = bh & 7, j = threadIdx.x;
    const BF* vp = kv + ((long)(b * 256 + j)) * 512 + 256 + h * 32;
    BF* o = vt + (long)bh * 8192 + j;
#pragma unroll
    for (int d = 0; d < 32; d++) o[d * 256] = vp[d];
}

// ---------------- bf16 MMA GEMM, BK=64, cp.async 3-stage ----------------
__device__ __forceinline__ void issue_tile(const BF* Ap, const BF* Bp, long ko,
                                           char* sA, char* sB, int tid, int lda, int ldb) {
#pragma unroll
    for (int i = 0; i < 4; i++) {
        int idx = tid + 256 * i, row = idx >> 3, seg = idx & 7;
        uint32_t da = (uint32_t)__cvta_generic_to_shared(sA + (row * 72 + seg * 8) * 2);
        CP_ASYNC16(da, Ap + (long)row * lda + ko + seg * 8);
        uint32_t db = (uint32_t)__cvta_generic_to_shared(sB + (row * 72 + seg * 8) * 2);
        CP_ASYNC16(db, Bp + (long)row * ldb + ko + seg * 8);
    }
}

template <int EPI>
__global__ void __launch_bounds__(256, 2) gemm_k(
    const BF* __restrict__ A, int lda, const BF* __restrict__ Bm, int ldb, int kChunks,
    float* __restrict__ Cf, BF* __restrict__ Cb, int ldc,
    const float* __restrict__ resid, const float* __restrict__ gp)
{
    extern __shared__ __align__(16) char smem[];

    int tid = threadIdx.x, warp = tid >> 5, lane = tid & 31;
    int wm = warp & 3, wn = warp >> 2;
    int lq = lane >> 2, lr = lane & 3;
    long m0 = (long)blockIdx.x * 128;
    int n0 = blockIdx.y * 128;
    long kOff = (EPI == 3) ? 0 : (long)blockIdx.z * kChunks * 64;
    long bOff = (EPI == 3) ? (long)blockIdx.z * 1048576 : 0;

    const BF* Ap = A + m0 * lda + kOff;
    const BF* Bp = Bm + bOff + (long)n0 * ldb + kOff;

    float acc[2][8][4];
#pragma unroll
    for (int i = 0; i < 2; i++)
#pragma unroll
        for (int j = 0; j < 8; j++)
#pragma unroll
            for (int q = 0; q < 4; q++) acc[i][j][q] = 0.f;

    issue_tile(Ap, Bp, 0, smem, smem + 18432, tid, lda, ldb);
    CP_COMMIT();
    if (kChunks > 1)
        issue_tile(Ap, Bp, 64, smem + 36864, smem + 36864 + 18432, tid, lda, ldb);
    CP_COMMIT();

    for (int ch = 0; ch < kChunks; ch++) {
        CP_WAIT1();
        __syncthreads();
        if (ch + 2 < kChunks) {
            int st = (ch + 2) % 3;
            issue_tile(Ap, Bp, (long)(ch + 2) * 64, smem + st * 36864, smem + st * 36864 + 18432, tid, lda, ldb);
        }
        CP_COMMIT();
        BF* sA = (BF*)(smem + (ch % 3) * 36864);
        BF* sB = (BF*)(smem + (ch % 3) * 36864 + 18432);
#pragma unroll
        for (int ks = 0; ks < 4; ks++) {
            uint32_t af[2][4], bf[8][2], bq[4];
#pragma unroll
            for (int tm = 0; tm < 2; tm++)
                ldsmA(af[tm], sA, wm * 32 + tm * 16, ks * 16, 72, lane);
#pragma unroll
            for (int np = 0; np < 4; np++) {
                ldsmB(bq, sB, wn * 64 + np * 16, ks * 16, 72, lane);
                bf[2 * np][0] = bq[0]; bf[2 * np][1] = bq[1];
                bf[2 * np + 1][0] = bq[2]; bf[2 * np + 1][1] = bq[3];
            }
#pragma unroll
            for (int tm = 0; tm < 2; tm++)
#pragma unroll
                for (int nt = 0; nt < 8; nt++)
                    mma16816(acc[tm][nt], af[tm], bf[nt]);
        }
    }

    if (EPI == 0) {
        float* out = Cf + (long)blockIdx.z * 524288 + m0 * 256 + n0;
#pragma unroll
        for (int tm = 0; tm < 2; tm++)
#pragma unroll
            for (int nt = 0; nt < 8; nt++) {
                int m = wm * 32 + tm * 16 + lq, n = wn * 64 + nt * 8 + lr * 2;
                *(float2*)(out + (long)m * 256 + n) = make_float2(acc[tm][nt][0], acc[tm][nt][1]);
                *(float2*)(out + (long)(m + 8) * 256 + n) = make_float2(acc[tm][nt][2], acc[tm][nt][3]);
            }
    } else if (EPI == 1) {
#pragma unroll
        for (int tm = 0; tm < 2; tm++)
#pragma unroll
            for (int nt = 0; nt < 8; nt++) {
                int m = wm * 32 + tm * 16 + lq, n = wn * 64 + nt * 8 + lr * 2;
                *(uint32_t*)(Cb + (m0 + m) * ldc + n0 + n) = pk(acc[tm][nt][0], acc[tm][nt][1]);
                *(uint32_t*)(Cb + (m0 + m + 8) * ldc + n0 + n) = pk(acc[tm][nt][2], acc[tm][nt][3]);
            }
    } else {
        float g = gp[0];
        long base = (long)blockIdx.z * 1048576 + m0 * 4096 + n0;
        float* po = Cf + base;
        const float* pr = resid + base;
#pragma unroll
        for (int tm = 0; tm < 2; tm++)
#pragma unroll
            for (int nt = 0; nt < 8; nt++) {
                int m = wm * 32 + tm * 16 + lq, n = wn * 64 + nt * 8 + lr * 2;
                long a0 = (long)m * 4096 + n, a1 = (long)(m + 8) * 4096 + n;
                float2 r0 = *(const float2*)(pr + a0);
                float2 r1 = *(const float2*)(pr + a1);
                *(float2*)(po + a0) = make_float2(r0.x + g * acc[tm][nt][0], r0.y + g * acc[tm][nt][1]);
                *(float2*)(po + a1) = make_float2(r1.x + g * acc[tm][nt][2], r1.y + g * acc[tm][nt][3]);
            }
    }
}

// ---------------- fused attention: 256 queries/block, 8 warps ----------------
__global__ void __launch_bounds__(256) attn_k(const BF* __restrict__ q, const BF* __restrict__ kv,
                                              const BF* __restrict__ vt, BF* __restrict__ ao)
{
    extern __shared__ __align__(16) BF asm_[];
    BF* sQ = asm_;                 // 256*40 = 10240 BF = 20480 B
    BF* sK = asm_ + 10240;         // 256*40
    BF* sV = asm_ + 20480;         // 32*264 = 8448 BF

    int tid = threadIdx.x, warp = tid >> 5, lane = tid & 31;
    int lq = lane >> 2, lr = lane & 3;
    int bh = blockIdx.y, b = bh >> 3, h = bh & 7, n0 = blockIdx.x * 256;

    const BF* qp = q + ((long)(b * 4096 + n0)) * 256 + h * 32;
#pragma unroll
    for (int i = 0; i < 4; i++) {
        int idx = tid + 256 * i, row = idx >> 2, seg = idx & 3;   // 1024 uint4 = 256x32
        *(uint4*)(sQ + row * 40 + seg * 8) = *(const uint4*)(qp + (long)row * 256 + seg * 8);
    }
    const BF* kp = kv + ((long)(b * 256)) * 512 + h * 32;
#pragma unroll
    for (int i = 0; i < 4; i++) {
        int idx = tid + 256 * i, row = idx >> 2, seg = idx & 3;   // 1024 uint4 = 256x32
        *(uint4*)(sK + row * 40 + seg * 8) = *(const uint4*)(kp + (long)row * 512 + seg * 8);
    }
    const BF* vp = vt + (long)bh * 8192;
#pragma unroll
    for (int i = 0; i < 8; i++) {
        int idx = tid + 256 * i, row = idx >> 6, seg = idx & 63;  // 2048 uint2 = 32x256
        *(uint2*)(sV + row * 264 + seg * 4) = *(const uint2*)(vp + row * 256 + seg * 4);
    }
    __syncthreads();

    float oacc[2][4][4];
#pragma unroll
    for (int i = 0; i < 2; i++)
#pragma unroll
        for (int j = 0; j < 4; j++)
#pragma unroll
            for (int qd = 0; qd < 4; qd++) oacc[i][j][qd] = 0.f;
    float su[2][2] = {{0.f, 0.f}, {0.f, 0.f}};

    uint32_t af[2][4], af2[2][4];
#pragma unroll
    for (int tm = 0; tm < 2; tm++) {
        ldsmA(af[tm],  sQ, warp * 32 + tm * 16, 0,  40, lane);
        ldsmA(af2[tm], sQ, warp * 32 + tm * 16, 16, 40, lane);
    }

#pragma unroll 1
    for (int c = 0; c < 4; c++) {
        float sacc[2][8][4];
#pragma unroll
        for (int i = 0; i < 2; i++)
#pragma unroll
            for (int j = 0; j < 8; j++)
#pragma unroll
                for (int qd = 0; qd < 4; qd++) sacc[i][j][qd] = 0.f;

#pragma unroll
        for (int ks = 0; ks < 2; ks++) {
            uint32_t bf[8][2], bq[4];
#pragma unroll
            for (int np = 0; np < 4; np++) {
                ldsmB(bq, sK, c * 64 + np * 16, ks * 16, 40, lane);
                bf[2 * np][0] = bq[0]; bf[2 * np][1] = bq[1];
                bf[2 * np + 1][0] = bq[2]; bf[2 * np + 1][1] = bq[3];
            }
#pragma unroll
            for (int tm = 0; tm < 2; tm++)
#pragma unroll
                for (int nt = 0; nt < 8; nt++)
                    mma16816(sacc[tm][nt], ks ? af2[tm] : af[tm], bf[nt]);
        }
#pragma unroll
        for (int tm = 0; tm < 2; tm++)
#pragma unroll
            for (int nt = 0; nt < 8; nt++) {
                float e0 = __expf(sacc[tm][nt][0] * SCALE_);
                float e1 = __expf(sacc[tm][nt][1] * SCALE_);
                float e2 = __expf(sacc[tm][nt][2] * SCALE_);
                float e3 = __expf(sacc[tm][nt][3] * SCALE_);
                sacc[tm][nt][0] = e0; sacc[tm][nt][1] = e1;
                sacc[tm][nt][2] = e2; sacc[tm][nt][3] = e3;
                su[tm][0] += e0 + e1;
                su[tm][1] += e2 + e3;
            }
#pragma unroll
        for (int s = 0; s < 4; s++) {
            uint32_t pa[2][4];
#pragma unroll
            for (int tm = 0; tm < 2; tm++) {
                pa[tm][0] = pk(sacc[tm][2 * s][0], sacc[tm][2 * s][1]);
                pa[tm][1] = pk(sacc[tm][2 * s][2], sacc[tm][2 * s][3]);
                pa[tm][2] = pk(sacc[tm][2 * s + 1][0], sacc[tm][2 * s + 1][1]);
                pa[tm][3] = pk(sacc[tm][2 * s + 1][2], sacc[tm][2 * s + 1][3]);
            }
            uint32_t bv[4][2], bq[4];
#pragma unroll
            for (int np = 0; np < 2; np++) {
                ldsmB(bq, sV, np * 16, c * 64 + s * 16, 264, lane);
                bv[2 * np][0] = bq[0]; bv[2 * np][1] = bq[1];
                bv[2 * np + 1][0] = bq[2]; bv[2 * np + 1][1] = bq[3];
            }
#pragma unroll
            for (int tm = 0; tm < 2; tm++)
#pragma unroll
                for (int nd = 0; nd < 4; nd++)
                    mma16816(oacc[tm][nd], pa[tm], bv[nd]);
        }
    }

#pragma unroll
    for (int tm = 0; tm < 2; tm++)
#pragma unroll
        for (int hf = 0; hf < 2; hf++) {
            float s = su[tm][hf];
            s += __shfl_xor_sync(0xffffffffu, s, 1);
            s += __shfl_xor_sync(0xffffffffu, s, 2);
            su[tm][hf] = 1.f / s;
        }
    BF* op = ao + ((long)(b * 4096 + n0)) * 256 + h * 32;
#pragma unroll
    for (int tm = 0; tm < 2; tm++)
#pragma unroll
        for (int nd = 0; nd < 4; nd++) {
            int m = warp * 32 + tm * 16 + lq, n = nd * 8 + lr * 2;
            *(uint32_t*)(op + (long)m * 256 + n) =
                pk(oacc[tm][nd][0] * su[tm][0], oacc[tm][nd][1] * su[tm][0]);
            *(uint32_t*)(op + (long)(m + 8) * 256 + n) =
                pk(oacc[tm][nd][2] * su[tm][1], oacc[tm][nd][3] * su[tm][1]);
        }
}

// ---------------- launch: fork-join DAG ----------------
extern "C" void kernel_launch(void* const* d_in, const int* in_sizes, int n_in,
                              void* d_out, int out_size)
{
    const float* x    = (const float*)d_in[0];
    const float* w_q  = (const float*)d_in[1];
    const float* w_kv = (const float*)d_in[2];
    const float* w_sr = (const float*)d_in[3];
    const float* ng   = (const float*)d_in[4];
    const float* nb   = (const float*)d_in[5];
    const float* w_o  = (const float*)d_in[6];
    const float* gam  = (const float*)d_in[7];
    float* out = (float*)d_out;

    BF *A, *wsr, *wq, *wkv, *wo, *xr, *kv, *xT, *qb, *ao, *vt;
    float* prt;
    cudaGetSymbolAddress((void**)&A, g_A);     cudaGetSymbolAddress((void**)&wsr, g_wsr);
    cudaGetSymbolAddress((void**)&wq, g_wq);   cudaGetSymbolAddress((void**)&wkv, g_wkv);
    cudaGetSymbolAddress((void**)&wo, g_wo);   cudaGetSymbolAddress((void**)&prt, g_prt);
    cudaGetSymbolAddress((void**)&xr, g_xr);   cudaGetSymbolAddress((void**)&kv, g_kv);
    cudaGetSymbolAddress((void**)&xT, g_xT);   cudaGetSymbolAddress((void**)&qb, g_qb);
    cudaGetSymbolAddress((void**)&ao, g_ao);   cudaGetSymbolAddress((void**)&vt, g_vt);

    const int GSM = 110592;
    const int ASM = 57856;   // sQ 20480 + sK 20480 + sV 16896
    cudaFuncSetAttribute(gemm_k<0>, cudaFuncAttributeMaxDynamicSharedMemorySize, GSM);
    cudaFuncSetAttribute(gemm_k<1>, cudaFuncAttributeMaxDynamicSharedMemorySize, GSM);
    cudaFuncSetAttribute(gemm_k<3>, cudaFuncAttributeMaxDynamicSharedMemorySize, GSM);
    cudaFuncSetAttribute(attn_k,    cudaFuncAttributeMaxDynamicSharedMemorySize, ASM);

    cudaStream_t sB;
    cudaEvent_t e0, eB;
    cudaStreamCreateWithFlags(&sB, cudaStreamNonBlocking);
    cudaEventCreateWithFlags(&e0, cudaEventDisableTiming);
    cudaEventCreateWithFlags(&eB, cudaEventDisableTiming);

    prep_k<<<2304, 256>>>(x, w_q, w_kv, w_sr, w_o, wq, wkv, wsr, wo, A, xT);
    cudaEventRecord(e0, 0);

    cudaStreamWaitEvent(sB, e0, 0);
    gemm_k<1><<<dim3(256, 2, 1), 256, GSM, sB>>>(xT, 256, wq, 256, 4, nullptr, qb, 256, nullptr, nullptr);
    cudaEventRecord(eB, sB);

    gemm_k<0><<<dim3(16, 2, 8), 256, GSM>>>(A, 4096, wsr, 4096, 8, prt, nullptr, 0, nullptr, nullptr);
    lnred_k<<<512, 256>>>(prt, ng, nb, xr);
    gemm_k<1><<<dim3(16, 4, 1), 256, GSM>>>(xr, 256, wkv, 256, 4, nullptr, kv, 512, nullptr, nullptr);
    vtp_k<<<64, 256>>>(kv, vt);

    cudaStreamWaitEvent(0, eB, 0);
    attn_k<<<dim3(16, 64), 256, ASM>>>(qb, kv, vt, ao);
    gemm_k<3><<<dim3(2, 32, 8), 256, GSM>>>(wo, 256, ao, 256, 4, out, nullptr, 0, x, gam);

    cudaStreamDestroy(sB);
    cudaEventDestroy(e0);
    cudaEventDestroy(eB);
}

// round 16
// speedup vs baseline: 1.0495x; 1.0495x over previous
#include <cuda_runtime.h>
#include <cuda_bf16.h>
#include <cstdint>

#define BF __nv_bfloat16
#define SCALE_ 0.17677669529663687f

// ---------------- scratch ----------------
__device__ __align__(16) BF    g_A  [2048u*4096u];
__device__ __align__(16) BF    g_wsr[1048576];
__device__ __align__(16) BF    g_wq [65536], g_wkv[131072], g_wo[65536];
__device__ __align__(16) float g_prt[8u*2048u*256u];
__device__ __align__(16) BF    g_xr [2048u*256u];
__device__ __align__(16) BF    g_kv [2048u*512u];
__device__ __align__(16) BF    g_xT [32768u*256u];
__device__ __align__(16) BF    g_qb [32768u*256u];
__device__ __align__(16) BF    g_ao [32768u*256u];
__device__ __align__(16) BF    g_vt [64u*8192u];

__device__ __forceinline__ uint32_t pk(float a, float b) {
    __nv_bfloat162 t; t.x = __float2bfloat16(a); t.y = __float2bfloat16(b);
    return *reinterpret_cast<uint32_t*>(&t);
}
__device__ __forceinline__ void mma16816(float* d, const uint32_t* a, const uint32_t* b) {
    asm volatile("mma.sync.aligned.m16n8k16.row.col.f32.bf16.bf16.f32 "
                 "{%0,%1,%2,%3}, {%4,%5,%6,%7}, {%8,%9}, {%0,%1,%2,%3};"
                 : "+f"(d[0]), "+f"(d[1]), "+f"(d[2]), "+f"(d[3])
                 : "r"(a[0]), "r"(a[1]), "r"(a[2]), "r"(a[3]), "r"(b[0]), "r"(b[1]));
}
__device__ __forceinline__ void ldsm4(uint32_t* r, const BF* p) {
    uint32_t a = (uint32_t)__cvta_generic_to_shared(p);
    asm volatile("ldmatrix.sync.aligned.m8n8.x4.shared.b16 {%0,%1,%2,%3}, [%4];"
                 : "=r"(r[0]), "=r"(r[1]), "=r"(r[2]), "=r"(r[3]) : "r"(a));
}
__device__ __forceinline__ void ldsmA(uint32_t* r, const BF* base, int mb, int kb, int ld, int lane) {
    int sel = lane >> 3, i = lane & 7;
    ldsm4(r, base + (mb + ((sel & 1) << 3) + i) * ld + kb + ((sel >> 1) << 3));
}
__device__ __forceinline__ void ldsmB(uint32_t* r, const BF* base, int nb, int kb, int ld, int lane) {
    int sel = lane >> 3, i = lane & 7;
    ldsm4(r, base + (nb + ((sel >> 1) << 3) + i) * ld + kb + ((sel & 1) << 3));
}
#define CP_ASYNC16(dst, src) \
    asm volatile("cp.async.cg.shared.global [%0], [%1], 16;\n" :: "r"(dst), "l"(src))
#define CP_COMMIT() asm volatile("cp.async.commit_group;\n" ::: "memory")
#define CP_WAIT1()  asm volatile("cp.async.wait_group 1;\n" ::: "memory")

// ---------------- merged prep ----------------
__global__ void prep_k(const float* __restrict__ x,
                       const float* __restrict__ wq, const float* __restrict__ wkv,
                       const float* __restrict__ wsr, const float* __restrict__ wo,
                       BF* __restrict__ dq, BF* __restrict__ dkv,
                       BF* __restrict__ dsr, BF* __restrict__ dwo,
                       BF* __restrict__ A, BF* __restrict__ T)
{
    __shared__ __align__(16) BF sm[32 * 264];
    int bx = blockIdx.x, tid = threadIdx.x;
    if (bx < 1280) {
        int i = bx * 256 + tid;
        const float* s; BF* d; int o;
        if (i < 16384)       { s = wq;  d = dq;  o = i; }
        else if (i < 49152)  { s = wkv; d = dkv; o = i - 16384; }
        else if (i < 311296) { s = wsr; d = dsr; o = i - 49152; }
        else                 { s = wo;  d = dwo; o = i - 311296; }
        float4 v = ((const float4*)s)[o];
        ((uint2*)d)[o] = make_uint2(pk(v.x, v.y), pk(v.z, v.w));
    } else {
        int idx = bx - 1280;
        int c0 = (idx & 7) * 32, i = (idx >> 3) & 15, b = idx >> 7;
#pragma unroll
        for (int it = 0; it < 32; it++) {
            int g = tid + 256 * it;
            int col = g & 255, cc = g >> 8;
            float v = x[(long)b * 1048576 + (long)(c0 + cc) * 4096 + i * 256 + col];
            sm[cc * 264 + col] = __float2bfloat16(v);
        }
        __syncthreads();
#pragma unroll
        for (int it = 0; it < 4; it++) {
            int g = tid + 256 * it;
            int j = g >> 6, rem = g & 63;
            int cc = rem >> 1, hb = (rem & 1) * 2;
            __align__(16) BF tmp[8];
#pragma unroll
            for (int r1o = 0; r1o < 2; r1o++)
#pragma unroll
                for (int r2 = 0; r2 < 4; r2++)
                    tmp[r1o * 4 + r2] = sm[cc * 264 + (hb + r1o) * 64 + 4 * j + r2];
            *(uint4*)(A + ((long)(b * 256 + i * 16 + j)) * 4096 + c0 * 16 + rem * 8) = *(uint4*)tmp;
        }
#pragma unroll
        for (int it = 0; it < 4; it++) {
            int g = tid + 256 * it;
            int nl = g >> 2, c8 = g & 3;
            __align__(16) BF tmp[8];
#pragma unroll
            for (int t = 0; t < 8; t++) tmp[t] = sm[(c8 * 8 + t) * 264 + nl];
            *(uint4*)(T + ((long)(b * 4096 + i * 256 + nl)) * 256 + c0 + c8 * 8) = *(uint4*)tmp;
        }
    }
}
__global__ void lnred_k(const float* __restrict__ part, const float* __restrict__ gam,
                        const float* __restrict__ bet, BF* __restrict__ o) {
    __shared__ float sm1[4][2], sm2[4][2];
    int tid = threadIdx.x;
    int r = tid >> 6, t64 = tid & 63, lane = tid & 31, wir = (tid >> 5) & 1;
    int p = blockIdx.x * 4 + r;
    long base = (long)p * 256 + t64 * 4;
    float4 v = make_float4(0.f, 0.f, 0.f, 0.f);
#pragma unroll
    for (int z = 0; z < 8; z++) {
        float4 t = *(const float4*)(part + (long)z * 524288 + base);
        v.x += t.x; v.y += t.y; v.z += t.z; v.w += t.w;
    }
    float s1 = v.x + v.y + v.z + v.w;
    float s2 = v.x * v.x + v.y * v.y + v.z * v.z + v.w * v.w;
#pragma unroll
    for (int off = 16; off; off >>= 1) {
        s1 += __shfl_xor_sync(0xffffffffu, s1, off);
        s2 += __shfl_xor_sync(0xffffffffu, s2, off);
    }
    if (lane == 0) { sm1[r][wir] = s1; sm2[r][wir] = s2; }
    __syncthreads();
    float a = sm1[r][0] + sm1[r][1];
    float q = sm2[r][0] + sm2[r][1];
    float mu = a * (1.f / 256.f);
    float inv = rsqrtf(q * (1.f / 256.f) - mu * mu + 1e-6f);
    float4 gv = *(const float4*)(gam + t64 * 4);
    float4 bv = *(const float4*)(bet + t64 * 4);
    uint2 w;
    w.x = pk((v.x - mu) * inv * gv.x + bv.x, (v.y - mu) * inv * gv.y + bv.y);
    w.y = pk((v.z - mu) * inv * gv.z + bv.z, (v.w - mu) * inv * gv.w + bv.w);
    *(uint2*)(o + base) = w;
}

// ---------------- bf16 MMA GEMM, BK=64, cp.async 3-stage ----------------
// EPI 0: f32 split-K partials  EPI 1: bf16 row-major
// EPI 2: kv store (K half -> Cb; V half -> transposed vt)  EPI 3: direct residual
__device__ __forceinline__ void issue_tile(const BF* Ap, const BF* Bp, long ko,
                                           char* sA, char* sB, int tid, int lda, int ldb) {
#pragma unroll
    for (int i = 0; i < 4; i++) {
        int idx = tid + 256 * i, row = idx >> 3, seg = idx & 7;
        uint32_t da = (uint32_t)__cvta_generic_to_shared(sA + (row * 72 + seg * 8) * 2);
        CP_ASYNC16(da, Ap + (long)row * lda + ko + seg * 8);
        uint32_t db = (uint32_t)__cvta_generic_to_shared(sB + (row * 72 + seg * 8) * 2);
        CP_ASYNC16(db, Bp + (long)row * ldb + ko + seg * 8);
    }
}

template <int EPI>
__global__ void __launch_bounds__(256, 2) gemm_k(
    const BF* __restrict__ A, int lda, const BF* __restrict__ Bm, int ldb, int kChunks,
    float* __restrict__ Cf, BF* __restrict__ Cb, int ldc,
    const float* __restrict__ resid, const float* __restrict__ gp)
{
    extern __shared__ __align__(16) char smem[];

    int tid = threadIdx.x, warp = tid >> 5, lane = tid & 31;
    int wm = warp & 3, wn = warp >> 2;
    int lq = lane >> 2, lr = lane & 3;
    long m0 = (long)blockIdx.x * 128;
    int n0 = blockIdx.y * 128;
    long kOff = (EPI == 3) ? 0 : (long)blockIdx.z * kChunks * 64;
    long bOff = (EPI == 3) ? (long)blockIdx.z * 1048576 : 0;

    const BF* Ap = A + m0 * lda + kOff;
    const BF* Bp = Bm + bOff + (long)n0 * ldb + kOff;

    float acc[2][8][4];
#pragma unroll
    for (int i = 0; i < 2; i++)
#pragma unroll
        for (int j = 0; j < 8; j++)
#pragma unroll
            for (int q = 0; q < 4; q++) acc[i][j][q] = 0.f;

    issue_tile(Ap, Bp, 0, smem, smem + 18432, tid, lda, ldb);
    CP_COMMIT();
    if (kChunks > 1)
        issue_tile(Ap, Bp, 64, smem + 36864, smem + 36864 + 18432, tid, lda, ldb);
    CP_COMMIT();

    for (int ch = 0; ch < kChunks; ch++) {
        CP_WAIT1();
        __syncthreads();
        if (ch + 2 < kChunks) {
            int st = (ch + 2) % 3;
            issue_tile(Ap, Bp, (long)(ch + 2) * 64, smem + st * 36864, smem + st * 36864 + 18432, tid, lda, ldb);
        }
        CP_COMMIT();
        BF* sA = (BF*)(smem + (ch % 3) * 36864);
        BF* sB = (BF*)(smem + (ch % 3) * 36864 + 18432);
#pragma unroll
        for (int ks = 0; ks < 4; ks++) {
            uint32_t af[2][4], bf[8][2], bq[4];
#pragma unroll
            for (int tm = 0; tm < 2; tm++)
                ldsmA(af[tm], sA, wm * 32 + tm * 16, ks * 16, 72, lane);
#pragma unroll
            for (int np = 0; np < 4; np++) {
                ldsmB(bq, sB, wn * 64 + np * 16, ks * 16, 72, lane);
                bf[2 * np][0] = bq[0]; bf[2 * np][1] = bq[1];
                bf[2 * np + 1][0] = bq[2]; bf[2 * np + 1][1] = bq[3];
            }
#pragma unroll
            for (int tm = 0; tm < 2; tm++)
#pragma unroll
                for (int nt = 0; nt < 8; nt++)
                    mma16816(acc[tm][nt], af[tm], bf[nt]);
        }
    }

    if (EPI == 0) {
        float* out = Cf + (long)blockIdx.z * 524288 + m0 * 256 + n0;
#pragma unroll
        for (int tm = 0; tm < 2; tm++)
#pragma unroll
            for (int nt = 0; nt < 8; nt++) {
                int m = wm * 32 + tm * 16 + lq, n = wn * 64 + nt * 8 + lr * 2;
                *(float2*)(out + (long)m * 256 + n) = make_float2(acc[tm][nt][0], acc[tm][nt][1]);
                *(float2*)(out + (long)(m + 8) * 256 + n) = make_float2(acc[tm][nt][2], acc[tm][nt][3]);
            }
    } else if (EPI == 1) {
#pragma unroll
        for (int tm = 0; tm < 2; tm++)
#pragma unroll
            for (int nt = 0; nt < 8; nt++) {
                int m = wm * 32 + tm * 16 + lq, n = wn * 64 + nt * 8 + lr * 2;
                *(uint32_t*)(Cb + (m0 + m) * ldc + n0 + n) = pk(acc[tm][nt][0], acc[tm][nt][1]);
                *(uint32_t*)(Cb + (m0 + m + 8) * ldc + n0 + n) = pk(acc[tm][nt][2], acc[tm][nt][3]);
            }
    } else if (EPI == 2) {
        if (n0 < 256) {
            // K half -> g_kv rows
#pragma unroll
            for (int tm = 0; tm < 2; tm++)
#pragma unroll
                for (int nt = 0; nt < 8; nt++) {
                    int m = wm * 32 + tm * 16 + lq, n = wn * 64 + nt * 8 + lr * 2;
                    *(uint32_t*)(Cb + (m0 + m) * ldc + n0 + n) = pk(acc[tm][nt][0], acc[tm][nt][1]);
                    *(uint32_t*)(Cb + (m0 + m + 8) * ldc + n0 + n) = pk(acc[tm][nt][2], acc[tm][nt][3]);
                }
        } else {
            // V half -> smem transpose -> vt[bh][d][pix] (Cf reused as BF* vt via resid ptr? use gp trick)
            BF* st = (BF*)smem;   // [128 n][136 m] BF
            __syncthreads();
#pragma unroll
            for (int tm = 0; tm < 2; tm++)
#pragma unroll
                for (int nt = 0; nt < 8; nt++) {
                    int m = wm * 32 + tm * 16 + lq, n = wn * 64 + nt * 8 + lr * 2;
                    st[n * 136 + m]       = __float2bfloat16(acc[tm][nt][0]);
                    st[(n + 1) * 136 + m] = __float2bfloat16(acc[tm][nt][1]);
                    st[n * 136 + m + 8]       = __float2bfloat16(acc[tm][nt][2]);
                    st[(n + 1) * 136 + m + 8] = __float2bfloat16(acc[tm][nt][3]);
                }
            __syncthreads();
            BF* vt = (BF*)Cf;
            int b = (int)(m0 >> 8), pix0 = (int)(m0 & 255);
            int vbase = n0 - 256;
#pragma unroll
            for (int it = 0; it < 8; it++) {
                int idx = tid + 256 * it;         // 2048 uint4 = 128 rows x 16
                int nl = idx >> 4, m8 = idx & 15;
                int oc = vbase + nl;
                int bh = b * 8 + (oc >> 5), d = oc & 31;
                *(uint4*)(vt + (long)bh * 8192 + d * 256 + pix0 + m8 * 8) =
                    *(const uint4*)(st + nl * 136 + m8 * 8);
            }
        }
    } else {
        float g = gp[0];
        long base = (long)blockIdx.z * 1048576 + m0 * 4096 + n0;
        float* po = Cf + base;
        const float* pr = resid + base;
#pragma unroll
        for (int tm = 0; tm < 2; tm++)
#pragma unroll
            for (int nt = 0; nt < 8; nt++) {
                int m = wm * 32 + tm * 16 + lq, n = wn * 64 + nt * 8 + lr * 2;
                long a0 = (long)m * 4096 + n, a1 = (long)(m + 8) * 4096 + n;
                float2 r0 = *(const float2*)(pr + a0);
                float2 r1 = *(const float2*)(pr + a1);
                *(float2*)(po + a0) = make_float2(r0.x + g * acc[tm][nt][0], r0.y + g * acc[tm][nt][1]);
                *(float2*)(po + a1) = make_float2(r1.x + g * acc[tm][nt][2], r1.y + g * acc[tm][nt][3]);
            }
    }
}

// ---------------- fused attention (R14 form: 128 threads, 128 queries) ----------------
__global__ void __launch_bounds__(128) attn_k(const BF* __restrict__ q, const BF* __restrict__ kv,
                                              const BF* __restrict__ vt, BF* __restrict__ ao)
{
    __shared__ __align__(16) BF sQ[128 * 40];
    __shared__ __align__(16) BF sK[256 * 40];
    __shared__ __align__(16) BF sV[32 * 264];

    int tid = threadIdx.x, warp = tid >> 5, lane = tid & 31;
    int lq = lane >> 2, lr = lane & 3;
    int bh = blockIdx.y, b = bh >> 3, h = bh & 7, n0 = blockIdx.x * 128;

    const BF* qp = q + ((long)(b * 4096 + n0)) * 256 + h * 32;
#pragma unroll
    for (int i = 0; i < 4; i++) {
        int idx = tid + 128 * i, row = idx >> 2, seg = idx & 3;
        *(uint4*)(sQ + row * 40 + seg * 8) = *(const uint4*)(qp + (long)row * 256 + seg * 8);
    }
    const BF* kp = kv + ((long)(b * 256)) * 512 + h * 32;
#pragma unroll
    for (int i = 0; i < 8; i++) {
        int idx = tid + 128 * i, row = idx >> 2, seg = idx & 3;
        *(uint4*)(sK + row * 40 + seg * 8) = *(const uint4*)(kp + (long)row * 512 + seg * 8);
    }
    const BF* vp = vt + (long)bh * 8192;
#pragma unroll
    for (int i = 0; i < 16; i++) {
        int idx = tid + 128 * i, row = idx >> 6, seg = idx & 63;
        *(uint2*)(sV + row * 264 + seg * 4) = *(const uint2*)(vp + row * 256 + seg * 4);
    }
    __syncthreads();

    float oacc[2][4][4];
#pragma unroll
    for (int i = 0; i < 2; i++)
#pragma unroll
        for (int j = 0; j < 4; j++)
#pragma unroll
            for (int qd = 0; qd < 4; qd++) oacc[i][j][qd] = 0.f;
    float su[2][2] = {{0.f, 0.f}, {0.f, 0.f}};

    uint32_t af[2][4], af2[2][4];
#pragma unroll
    for (int tm = 0; tm < 2; tm++) {
        ldsmA(af[tm],  sQ, warp * 32 + tm * 16, 0,  40, lane);
        ldsmA(af2[tm], sQ, warp * 32 + tm * 16, 16, 40, lane);
    }

#pragma unroll 1
    for (int c = 0; c < 4; c++) {
        float sacc[2][8][4];
#pragma unroll
        for (int i = 0; i < 2; i++)
#pragma unroll
            for (int j = 0; j < 8; j++)
#pragma unroll
                for (int qd = 0; qd < 4; qd++) sacc[i][j][qd] = 0.f;

#pragma unroll
        for (int ks = 0; ks < 2; ks++) {
            uint32_t bf[8][2], bq[4];
#pragma unroll
            for (int np = 0; np < 4; np++) {
                ldsmB(bq, sK, c * 64 + np * 16, ks * 16, 40, lane);
                bf[2 * np][0] = bq[0]; bf[2 * np][1] = bq[1];
                bf[2 * np + 1][0] = bq[2]; bf[2 * np + 1][1] = bq[3];
            }
#pragma unroll
            for (int tm = 0; tm < 2; tm++)
#pragma unroll
                for (int nt = 0; nt < 8; nt++)
                    mma16816(sacc[tm][nt], ks ? af2[tm] : af[tm], bf[nt]);
        }
#pragma unroll
        for (int tm = 0; tm < 2; tm++)
#pragma unroll
            for (int nt = 0; nt < 8; nt++) {
                float e0 = __expf(sacc[tm][nt][0] * SCALE_);
                float e1 = __expf(sacc[tm][nt][1] * SCALE_);
                float e2 = __expf(sacc[tm][nt][2] * SCALE_);
                float e3 = __expf(sacc[tm][nt][3] * SCALE_);
                sacc[tm][nt][0] = e0; sacc[tm][nt][1] = e1;
                sacc[tm][nt][2] = e2; sacc[tm][nt][3] = e3;
                su[tm][0] += e0 + e1;
                su[tm][1] += e2 + e3;
            }
#pragma unroll
        for (int s = 0; s < 4; s++) {
            uint32_t pa[2][4];
#pragma unroll
            for (int tm = 0; tm < 2; tm++) {
                pa[tm][0] = pk(sacc[tm][2 * s][0], sacc[tm][2 * s][1]);
                pa[tm][1] = pk(sacc[tm][2 * s][2], sacc[tm][2 * s][3]);
                pa[tm][2] = pk(sacc[tm][2 * s + 1][0], sacc[tm][2 * s + 1][1]);
                pa[tm][3] = pk(sacc[tm][2 * s + 1][2], sacc[tm][2 * s + 1][3]);
            }
            uint32_t bv[4][2], bq[4];
#pragma unroll
            for (int np = 0; np < 2; np++) {
                ldsmB(bq, sV, np * 16, c * 64 + s * 16, 264, lane);
                bv[2 * np][0] = bq[0]; bv[2 * np][1] = bq[1];
                bv[2 * np + 1][0] = bq[2]; bv[2 * np + 1][1] = bq[3];
            }
#pragma unroll
            for (int tm = 0; tm < 2; tm++)
#pragma unroll
                for (int nd = 0; nd < 4; nd++)
                    mma16816(oacc[tm][nd], pa[tm], bv[nd]);
        }
    }

#pragma unroll
    for (int tm = 0; tm < 2; tm++)
#pragma unroll
        for (int hf = 0; hf < 2; hf++) {
            float s = su[tm][hf];
            s += __shfl_xor_sync(0xffffffffu, s, 1);
            s += __shfl_xor_sync(0xffffffffu, s, 2);
            su[tm][hf] = 1.f / s;
        }
    BF* op = ao + ((long)(b * 4096 + n0)) * 256 + h * 32;
#pragma unroll
    for (int tm = 0; tm < 2; tm++)
#pragma unroll
        for (int nd = 0; nd < 4; nd++) {
            int m = warp * 32 + tm * 16 + lq, n = nd * 8 + lr * 2;
            *(uint32_t*)(op + (long)m * 256 + n) =
                pk(oacc[tm][nd][0] * su[tm][0], oacc[tm][nd][1] * su[tm][0]);
            *(uint32_t*)(op + (long)(m + 8) * 256 + n) =
                pk(oacc[tm][nd][2] * su[tm][1], oacc[tm][nd][3] * su[tm][1]);
        }
}

// ---------------- launch: fork-join DAG ----------------
extern "C" void kernel_launch(void* const* d_in, const int* in_sizes, int n_in,
                              void* d_out, int out_size)
{
    const float* x    = (const float*)d_in[0];
    const float* w_q  = (const float*)d_in[1];
    const float* w_kv = (const float*)d_in[2];
    const float* w_sr = (const float*)d_in[3];
    const float* ng   = (const float*)d_in[4];
    const float* nb   = (const float*)d_in[5];
    const float* w_o  = (const float*)d_in[6];
    const float* gam  = (const float*)d_in[7];
    float* out = (float*)d_out;

    BF *A, *wsr, *wq, *wkv, *wo, *xr, *kv, *xT, *qb, *ao, *vt;
    float* prt;
    cudaGetSymbolAddress((void**)&A, g_A);     cudaGetSymbolAddress((void**)&wsr, g_wsr);
    cudaGetSymbolAddress((void**)&wq, g_wq);   cudaGetSymbolAddress((void**)&wkv, g_wkv);
    cudaGetSymbolAddress((void**)&wo, g_wo);   cudaGetSymbolAddress((void**)&prt, g_prt);
    cudaGetSymbolAddress((void**)&xr, g_xr);   cudaGetSymbolAddress((void**)&kv, g_kv);
    cudaGetSymbolAddress((void**)&xT, g_xT);   cudaGetSymbolAddress((void**)&qb, g_qb);
    cudaGetSymbolAddress((void**)&ao, g_ao);   cudaGetSymbolAddress((void**)&vt, g_vt);

    const int GSM = 110592;
    cudaFuncSetAttribute(gemm_k<0>, cudaFuncAttributeMaxDynamicSharedMemorySize, GSM);
    cudaFuncSetAttribute(gemm_k<1>, cudaFuncAttributeMaxDynamicSharedMemorySize, GSM);
    cudaFuncSetAttribute(gemm_k<2>, cudaFuncAttributeMaxDynamicSharedMemorySize, GSM);
    cudaFuncSetAttribute(gemm_k<3>, cudaFuncAttributeMaxDynamicSharedMemorySize, GSM);

    cudaStream_t sB;
    cudaEvent_t e0, eB;
    cudaStreamCreateWithFlags(&sB, cudaStreamNonBlocking);
    cudaEventCreateWithFlags(&e0, cudaEventDisableTiming);
    cudaEventCreateWithFlags(&eB, cudaEventDisableTiming);

    prep_k<<<2304, 256>>>(x, w_q, w_kv, w_sr, w_o, wq, wkv, wsr, wo, A, xT);
    cudaEventRecord(e0, 0);

    cudaStreamWaitEvent(sB, e0, 0);
    gemm_k<1><<<dim3(256, 2, 1), 256, GSM, sB>>>(xT, 256, wq, 256, 4, nullptr, qb, 256, nullptr, nullptr);
    cudaEventRecord(eB, sB);

    gemm_k<0><<<dim3(16, 2, 8), 256, GSM>>>(A, 4096, wsr, 4096, 8, prt, nullptr, 0, nullptr, nullptr);
    lnred_k<<<512, 256>>>(prt, ng, nb, xr);
    // kv GEMM with fused V-transpose epilogue (vt passed via Cf slot)
    gemm_k<2><<<dim3(16, 4, 1), 256, GSM>>>(xr, 256, wkv, 256, 4, (float*)vt, kv, 512, nullptr, nullptr);

    cudaStreamWaitEvent(0, eB, 0);
    attn_k<<<dim3(32, 64), 128>>>(qb, kv, vt, ao);
    gemm_k<3><<<dim3(2, 32, 8), 256, GSM>>>(wo, 256, ao, 256, 4, out, nullptr, 0, x, gam);

    cudaStreamDestroy(sB);
    cudaEventDestroy(e0);
    cudaEventDestroy(eB);
}